// round 12
// baseline (speedup 1.0000x reference)
#include <cuda_runtime.h>
#include <cuda_bf16.h>
#include <math.h>
#include <stdint.h>

// ---------------- problem dims ----------------
#define BB   8
#define SEQ  1024
#define DM   1024
#define NH   16
#define DK   64
#define MROWS (BB*SEQ)
#define OUT_MAIN  (BB*SEQ*DM)
#define OUT_ATT   (BB*NH*SEQ*SEQ)

// ---------------- scratch ----------------
__device__ __align__(128) float g_y[OUT_MAIN];
__device__ __align__(128) float g_x[OUT_MAIN];
__device__ float g_att_fb[OUT_ATT];

__device__ __align__(128) __nv_bfloat16 g_ahi[MROWS*DM];
__device__ __align__(128) __nv_bfloat16 g_alo[MROWS*DM];
__device__ __align__(128) __nv_bfloat16 g_qh[MROWS*DM], g_ql[MROWS*DM];
__device__ __align__(128) __nv_bfloat16 g_kh[MROWS*DM], g_kl[MROWS*DM];
__device__ __align__(128) __nv_bfloat16 g_vh[MROWS*DM], g_vl[MROWS*DM];
__device__ __align__(128) __nv_bfloat16 g_wqh[DM*DM], g_wql[DM*DM];
__device__ __align__(128) __nv_bfloat16 g_wkh[DM*DM], g_wkl[DM*DM];
__device__ __align__(128) __nv_bfloat16 g_wvh[DM*DM], g_wvl[DM*DM];
__device__ __align__(128) __nv_bfloat16 g_woh[DM*DM], g_wol[DM*DM];
__device__ __align__(128) __nv_bfloat16 g_w1h[DM*DM], g_w1l[DM*DM];
__device__ __align__(128) __nv_bfloat16 g_w2h[DM*DM], g_w2l[DM*DM];

// ---------------- helpers ----------------
__device__ __forceinline__ uint32_t cvta_s(const void* p) {
    return (uint32_t)__cvta_generic_to_shared(p);
}
__device__ __forceinline__ void ldsm4(uint32_t r[4], uint32_t a) {
    asm volatile("ldmatrix.sync.aligned.m8n8.x4.shared.b16 {%0,%1,%2,%3}, [%4];"
                 : "=r"(r[0]), "=r"(r[1]), "=r"(r[2]), "=r"(r[3]) : "r"(a));
}
__device__ __forceinline__ void ldsm2(uint32_t r[2], uint32_t a) {
    asm volatile("ldmatrix.sync.aligned.m8n8.x2.shared.b16 {%0,%1}, [%2];"
                 : "=r"(r[0]), "=r"(r[1]) : "r"(a));
}
__device__ __forceinline__ void ldsm2t(uint32_t r[2], uint32_t a) {
    asm volatile("ldmatrix.sync.aligned.m8n8.x2.trans.shared.b16 {%0,%1}, [%2];"
                 : "=r"(r[0]), "=r"(r[1]) : "r"(a));
}
__device__ __forceinline__ void mma_bf16(float c[4], const uint32_t a[4], const uint32_t b[2]) {
    asm volatile(
        "mma.sync.aligned.m16n8k16.row.col.f32.bf16.bf16.f32 "
        "{%0,%1,%2,%3}, {%4,%5,%6,%7}, {%8,%9}, {%0,%1,%2,%3};"
        : "+f"(c[0]), "+f"(c[1]), "+f"(c[2]), "+f"(c[3])
        : "r"(a[0]), "r"(a[1]), "r"(a[2]), "r"(a[3]), "r"(b[0]), "r"(b[1]));
}
__device__ __forceinline__ void cp16(uint32_t d, const void* g) {
    asm volatile("cp.async.cg.shared.global [%0], [%1], 16;" :: "r"(d), "l"(g));
}
#define CP_COMMIT() asm volatile("cp.async.commit_group;" ::: "memory")

// ---------------- fast exp (FMA-only) ----------------
__device__ __forceinline__ float fast_exp(float x) {
    if (x < -87.0f) return 0.0f;
    float t  = x * 1.4426950408889634f;
    float fi = floorf(t);
    float f  = t - fi;
    float p  = 1.5403530e-4f;
    p = fmaf(p, f, 1.3333558e-3f);
    p = fmaf(p, f, 9.6181291e-3f);
    p = fmaf(p, f, 5.5504109e-2f);
    p = fmaf(p, f, 2.4022651e-1f);
    p = fmaf(p, f, 6.9314718e-1f);
    p = fmaf(p, f, 1.0f);
    return __int_as_float(((int)fi + 127) << 23) * p;
}

__device__ __forceinline__ void split2(float v0, float v1, __nv_bfloat162& h2, __nv_bfloat162& l2) {
    h2.x = __float2bfloat16(v0);
    h2.y = __float2bfloat16(v1);
    l2.x = __float2bfloat16(v0 - __bfloat162float(h2.x));
    l2.y = __float2bfloat16(v1 - __bfloat162float(h2.y));
}

// ---------------- batched split ----------------
__global__ void __launch_bounds__(256) splitmulti(
    const float* __restrict__ i0, const float* __restrict__ i1, const float* __restrict__ i2,
    __nv_bfloat16* __restrict__ h0, __nv_bfloat16* __restrict__ l0,
    __nv_bfloat16* __restrict__ h1, __nv_bfloat16* __restrict__ l1,
    __nv_bfloat16* __restrict__ h2p, __nv_bfloat16* __restrict__ l2p)
{
    const float* in; __nv_bfloat16 *hi, *lo;
    if      (blockIdx.y == 0) { in = i0; hi = h0;  lo = l0; }
    else if (blockIdx.y == 1) { in = i1; hi = h1;  lo = l1; }
    else                      { in = i2; hi = h2p; lo = l2p; }
    const int i = blockIdx.x * 256 + threadIdx.x;
    const float4 v = ((const float4*)in)[i];
    __nv_bfloat162 hA, lA, hB, lB;
    split2(v.x, v.y, hA, lA);
    split2(v.z, v.w, hB, lB);
    ((__nv_bfloat162*)hi)[i*2]   = hA;
    ((__nv_bfloat162*)hi)[i*2+1] = hB;
    ((__nv_bfloat162*)lo)[i*2]   = lA;
    ((__nv_bfloat162*)lo)[i*2+1] = lB;
}

__global__ void __launch_bounds__(256) split_transpose4(
    const float* __restrict__ i0, const float* __restrict__ i1,
    const float* __restrict__ i2, const float* __restrict__ i3,
    __nv_bfloat16* __restrict__ h0, __nv_bfloat16* __restrict__ l0,
    __nv_bfloat16* __restrict__ h1, __nv_bfloat16* __restrict__ l1,
    __nv_bfloat16* __restrict__ h2, __nv_bfloat16* __restrict__ l2,
    __nv_bfloat16* __restrict__ h3, __nv_bfloat16* __restrict__ l3)
{
    const float* in; __nv_bfloat16 *hi, *lo;
    if      (blockIdx.z == 0) { in = i0; hi = h0; lo = l0; }
    else if (blockIdx.z == 1) { in = i1; hi = h1; lo = l1; }
    else if (blockIdx.z == 2) { in = i2; hi = h2; lo = l2; }
    else                      { in = i3; hi = h3; lo = l3; }
    __shared__ float t[32][33];
    const int bx = blockIdx.x * 32, by = blockIdx.y * 32;
    const int txx = threadIdx.x, tyy = threadIdx.y;
#pragma unroll
    for (int j = 0; j < 32; j += 8)
        t[tyy + j][txx] = in[(by + tyy + j) * 1024 + bx + txx];
    __syncthreads();
#pragma unroll
    for (int j = 0; j < 32; j += 8) {
        const float v = t[txx][tyy + j];
        __nv_bfloat16 h = __float2bfloat16(v);
        __nv_bfloat16 l = __float2bfloat16(v - __bfloat162float(h));
        const int idx = (bx + tyy + j) * 1024 + by + txx;
        hi[idx] = h;
        lo[idx] = l;
    }
}

// ---------------- HMMA bf16x3 GEMM (k-chunk 16, 2 CTAs/SM) ----------------
#define ROWB2 48
#define ASTG2 6144
#define STG2  24576
#define GEMM_SMEM (2 * STG2)

template<int MODE>
__global__ void __launch_bounds__(256, 2) mma_gemm(
    const __nv_bfloat16* __restrict__ Ahi, const __nv_bfloat16* __restrict__ Alo,
    const __nv_bfloat16* __restrict__ Bhi, const __nv_bfloat16* __restrict__ Blo,
    float* __restrict__ C, const float* __restrict__ res, const float* __restrict__ bias,
    __nv_bfloat16* __restrict__ Chi, __nv_bfloat16* __restrict__ Clo)
{
    extern __shared__ __align__(128) char smem[];
    const int tid = threadIdx.x;
    const int lane = tid & 31, w = tid >> 5;
    const int wm = w >> 2, wn = w & 3;
    const int m0 = blockIdx.y * 128, n0 = blockIdx.x * 128;
    const uint32_t sbase = cvta_s(smem);

    float acc[4][4][4];
#pragma unroll
    for (int i = 0; i < 4; i++)
#pragma unroll
        for (int j = 0; j < 4; j++)
#pragma unroll
            for (int k = 0; k < 4; k++) acc[i][j][k] = 0.0f;

    const __nv_bfloat16* gsrc[4] = {Ahi, Alo, Bhi, Blo};

    auto fill = [&](int buf, int kc) {
        const int k0 = kc * 16;
        const uint32_t dst0 = sbase + buf * STG2;
#pragma unroll
        for (int i = 0; i < 4; i++) {
            const int idx = i * 256 + tid;       // 0..1023
            const int arr = idx >> 8;            // 0..3
            const int within = idx & 255;
            const int row = within >> 1, seg = within & 1;
            const int grow = (arr < 2 ? m0 : n0) + row;
            const __nv_bfloat16* g = gsrc[arr] + (long)grow * 1024 + k0 + seg * 8;
            cp16(dst0 + arr * ASTG2 + row * ROWB2 + seg * 16, g);
        }
        CP_COMMIT();
    };

    fill(0, 0);
    for (int c = 0; c < 64; c++) {
        const int buf = c & 1;
        if (c + 1 < 64) {
            fill(buf ^ 1, c + 1);
            asm volatile("cp.async.wait_group 1;" ::: "memory");
        } else {
            asm volatile("cp.async.wait_group 0;" ::: "memory");
        }
        __syncthreads();

        const uint32_t sb = sbase + buf * STG2;
        uint32_t ah[4][4], al[4][4], bh[4][2], bl[4][2];
        const int arow = lane & 15, ahalf = (lane >> 4) * 16;
#pragma unroll
        for (int mt = 0; mt < 4; mt++) {
            const uint32_t ao = sb + (wm * 64 + mt * 16 + arow) * ROWB2 + ahalf;
            ldsm4(ah[mt], ao);
            ldsm4(al[mt], ao + ASTG2);
        }
        const int le = lane & 15;
        const int bhalf = ((le >> 3) & 1) * 16, brow = le & 7;
#pragma unroll
        for (int nt = 0; nt < 4; nt++) {
            const uint32_t bo = sb + 2 * ASTG2 + (wn * 32 + nt * 8 + brow) * ROWB2 + bhalf;
            ldsm2(bh[nt], bo);
            ldsm2(bl[nt], bo + ASTG2);
        }
#pragma unroll
        for (int mt = 0; mt < 4; mt++)
#pragma unroll
            for (int nt = 0; nt < 4; nt++) {
                mma_bf16(acc[mt][nt], ah[mt], bh[nt]);
                mma_bf16(acc[mt][nt], ah[mt], bl[nt]);
                mma_bf16(acc[mt][nt], al[mt], bh[nt]);
            }
        __syncthreads();
    }

    // ---- epilogue ----
    const int g = lane >> 2, t4 = lane & 3;
#pragma unroll
    for (int mt = 0; mt < 4; mt++) {
#pragma unroll
        for (int half = 0; half < 2; half++) {
            const int m = m0 + wm * 64 + mt * 16 + g + half * 8;
#pragma unroll
            for (int nt = 0; nt < 4; nt++) {
                const int n = n0 + wn * 32 + nt * 8 + t4 * 2;
                float v0 = acc[mt][nt][half * 2 + 0];
                float v1 = acc[mt][nt][half * 2 + 1];
                if (MODE == 0) {
                    const int b = m >> 10, s = m & 1023, h = n >> 6, d = n & 63;
                    const long off = ((long)((b * 16 + h) * 1024 + s)) * 64 + d;
                    __nv_bfloat162 h2, l2;
                    split2(v0, v1, h2, l2);
                    *(__nv_bfloat162*)(Chi + off) = h2;
                    *(__nv_bfloat162*)(Clo + off) = l2;
                } else if (MODE == 1) {
                    const float2 r2 = *(const float2*)&res[(long)m * 1024 + n];
                    float2 o; o.x = v0 + r2.x; o.y = v1 + r2.y;
                    *(float2*)&C[(long)m * 1024 + n] = o;
                } else if (MODE == 2) {
                    const float2 bi = *(const float2*)&bias[n];
                    const float is2 = 0.70710678118654752f;
                    float x0 = v0 + bi.x, x1 = v1 + bi.y;
                    float g0 = 0.5f * x0 * (1.0f + erff(x0 * is2));
                    float g1 = 0.5f * x1 * (1.0f + erff(x1 * is2));
                    const long off = (long)m * 1024 + n;
                    __nv_bfloat162 h2, l2;
                    split2(g0, g1, h2, l2);
                    *(__nv_bfloat162*)(Chi + off) = h2;
                    *(__nv_bfloat162*)(Clo + off) = l2;
                } else {
                    const float2 bi = *(const float2*)&bias[n];
                    const float2 r2 = *(const float2*)&res[(long)m * 1024 + n];
                    float2 o; o.x = v0 + bi.x + r2.x; o.y = v1 + bi.y + r2.y;
                    *(float2*)&C[(long)m * 1024 + n] = o;
                }
            }
        }
    }
}

// ---------------- HMMA attention, 32 q-rows/block, packed P ----------------
#define AT_QH 0
#define AT_QL 4608
#define AT_KV 9216
#define AT_SS 46080
#define SSPW 1034
#define ATTN_SMEM (AT_SS + 32 * SSPW * 4)   // 178432

__global__ void __launch_bounds__(256) attn2(
    const __nv_bfloat16* __restrict__ qh, const __nv_bfloat16* __restrict__ ql,
    const __nv_bfloat16* __restrict__ kh, const __nv_bfloat16* __restrict__ kl,
    const __nv_bfloat16* __restrict__ vh, const __nv_bfloat16* __restrict__ vl,
    const unsigned char* __restrict__ mask,
    float* __restrict__ att,
    __nv_bfloat16* __restrict__ oh, __nv_bfloat16* __restrict__ ol)
{
    extern __shared__ __align__(128) char sm[];
    __shared__ int s_any;
    const uint32_t sbase = cvta_s(sm);
    const int tid = threadIdx.x;
    const int lane = tid & 31, w = tid >> 5;
    const int wm = w >> 2, wn = w & 3;
    const int qt = blockIdx.x, bh = blockIdx.y;
    const int b = bh >> 4, h = bh & 15;
    const int q0 = qt * 32;
    const long base = (long)bh * SEQ * 64;
    const float scale = 1.0f / (8.0f + 1e-6f);
    float* Ss = (float*)(sm + AT_SS);

    auto fillKV = [&](const __nv_bfloat16* phi_, const __nv_bfloat16* plo_, int buf, int kt) {
#pragma unroll
        for (int i = 0; i < 4; i++) {
            const int idx = i * 256 + tid;
            const int arr = idx >> 9;
            const int wi = idx & 511;
            const int row = wi >> 3, seg = wi & 7;
            const __nv_bfloat16* g = (arr ? plo_ : phi_) + base + (long)(kt * 64 + row) * 64 + seg * 8;
            cp16(sbase + AT_KV + buf * 18432 + arr * 9216 + row * 144 + seg * 16, g);
        }
        CP_COMMIT();
    };

    // Q hi/lo: 32 rows x 64, 512 cp16
#pragma unroll
    for (int i = 0; i < 2; i++) {
        const int idx = i * 256 + tid;
        const int arr = idx >> 8;
        const int wi = idx & 255;
        const int row = wi >> 3, seg = wi & 7;
        const __nv_bfloat16* g = (arr ? ql : qh) + base + (long)(q0 + row) * 64 + seg * 8;
        cp16(sbase + (arr ? AT_QL : AT_QH) + row * 144 + seg * 16, g);
    }
    if (tid == 0) s_any = 0;
    fillKV(kh, kl, 0, 0);

    if (tid < 32 && mask[b * SEQ + q0 + tid]) s_any = 1;

    const int kt_max = (q0 + 31) >> 6;

    // ---- phase 1: scores ----
    uint32_t ah[4][4], al[4][4];
    for (int kt = 0; kt <= kt_max; kt++) {
        const int buf = kt & 1;
        if (kt < kt_max) {
            fillKV(kh, kl, buf ^ 1, kt + 1);
            asm volatile("cp.async.wait_group 1;" ::: "memory");
        } else {
            asm volatile("cp.async.wait_group 0;" ::: "memory");
        }
        __syncthreads();
        if (kt == 0) {
#pragma unroll
            for (int s = 0; s < 4; s++) {
                const uint32_t qa = sbase + (wm * 16 + (lane & 15)) * 144 + s * 32 + (lane >> 4) * 16;
                ldsm4(ah[s], qa + AT_QH);
                ldsm4(al[s], qa + AT_QL);
            }
        }
        const uint32_t khb = sbase + AT_KV + buf * 18432;
        const int le = lane & 15;
#pragma unroll
        for (int j = 0; j < 2; j++) {
            float c[4] = {0, 0, 0, 0};
#pragma unroll
            for (int s = 0; s < 4; s++) {
                uint32_t bhr[2], blr[2];
                const uint32_t ka = khb + (wn * 16 + j * 8 + (le & 7)) * 144 + s * 32 + ((le >> 3) & 1) * 16;
                ldsm2(bhr, ka);
                ldsm2(blr, ka + 9216);
                mma_bf16(c, ah[s], bhr);
                mma_bf16(c, ah[s], blr);
                mma_bf16(c, al[s], bhr);
            }
            const int r = wm * 16 + (lane >> 2);
            const int col = kt * 64 + wn * 16 + j * 8 + (lane & 3) * 2;
            float2 st0; st0.x = c[0] * scale; st0.y = c[1] * scale;
            float2 st1; st1.x = c[2] * scale; st1.y = c[3] * scale;
            *(float2*)(Ss + r * SSPW + col) = st0;
            *(float2*)(Ss + (r + 8) * SSPW + col) = st1;
        }
        __syncthreads();
    }

    const int kt_end = s_any ? (SEQ / 64 - 1) : kt_max;

    fillKV(vh, vl, 0, 0);   // prefetch V chunk 0 under softmax

    // ---- phase 2: softmax (8 threads/row), pack p -> (bf16 hi, bf16 lo) in place ----
    {
        const int r = tid >> 3, tc = tid & 7;
        const int qg = q0 + r;
        const int limit = qg;
        const bool rmask = mask[b * SEQ + qg] != 0;
        float* srow = Ss + r * SSPW;

        float mx = -3.4e38f;
#pragma unroll 4
        for (int j = 0; j < 128; j++) {
            const int k = tc + (j << 3);
            if (k <= limit) mx = fmaxf(mx, srow[k]);
        }
#pragma unroll
        for (int off = 4; off; off >>= 1)
            mx = fmaxf(mx, __shfl_xor_sync(0xffffffffu, mx, off, 8));

        float l = 0.0f;
#pragma unroll 4
        for (int j = 0; j < 128; j++) {
            const int k = tc + (j << 3);
            if (k <= limit) {
                const float e = fast_exp(srow[k] - mx);
                srow[k] = e;
                l += e;
            }
        }
#pragma unroll
        for (int off = 4; off; off >>= 1)
            l += __shfl_xor_sync(0xffffffffu, l, off, 8);
        const float inv = 1.0f / l;
        const float invS = 1.0f / (float)SEQ;

        float* attrow = att + ((long)bh * SEQ + qg) * SEQ;
        uint32_t* prow = (uint32_t*)srow;
#pragma unroll 4
        for (int j = 0; j < 128; j++) {
            const int k = tc + (j << 3);
            float p;
            if (rmask)           p = invS;
            else if (k <= limit) p = srow[k] * inv;
            else                 p = 0.0f;
            attrow[k] = p;
            const __nv_bfloat16 phi = __float2bfloat16(p);
            const __nv_bfloat16 plo = __float2bfloat16(p - __bfloat162float(phi));
            prow[k] = (uint32_t)__bfloat16_as_ushort(phi) |
                      ((uint32_t)__bfloat16_as_ushort(plo) << 16);
        }
    }
    __syncthreads();

    // ---- phase 3: AV ----
    float oacc[2][4];
#pragma unroll
    for (int j = 0; j < 2; j++)
#pragma unroll
        for (int k = 0; k < 4; k++) oacc[j][k] = 0.0f;

    const int g = lane >> 2, t4 = lane & 3;
    for (int kt = 0; kt <= kt_end; kt++) {
        const int buf = kt & 1;
        if (kt < kt_end) {
            fillKV(vh, vl, buf ^ 1, kt + 1);
            asm volatile("cp.async.wait_group 1;" ::: "memory");
        } else {
            asm volatile("cp.async.wait_group 0;" ::: "memory");
        }
        __syncthreads();
        const uint32_t vbh = sbase + AT_KV + buf * 18432;
#pragma unroll
        for (int s = 0; s < 4; s++) {
            // P fragments from packed smem
            uint32_t pa[4], pb[4];
#pragma unroll
            for (int kk = 0; kk < 2; kk++) {
#pragma unroll
                for (int mi = 0; mi < 2; mi++) {
                    const int row = wm * 16 + g + mi * 8;
                    const int col = kt * 64 + s * 16 + kk * 8 + t4 * 2;
                    const uint2 ww = *(const uint2*)(Ss + row * SSPW + col);
                    const int fi = kk * 2 + mi;
                    pa[fi] = __byte_perm(ww.x, ww.y, 0x5410);
                    pb[fi] = __byte_perm(ww.x, ww.y, 0x7632);
                }
            }
#pragma unroll
            for (int j = 0; j < 2; j++) {
                uint32_t vvh[2], vvl[2];
                const uint32_t va = vbh + (s * 16 + (lane & 15)) * 144 + wn * 32 + j * 16;
                ldsm2t(vvh, va);
                ldsm2t(vvl, va + 9216);
                mma_bf16(oacc[j], pa, vvh);
                mma_bf16(oacc[j], pa, vvl);
                mma_bf16(oacc[j], pb, vvh);
            }
        }
        __syncthreads();
    }

    // epilogue: bf16 hi/lo direct to [M][1024]
#pragma unroll
    for (int j = 0; j < 2; j++) {
        const int dv = h * 64 + wn * 16 + j * 8 + t4 * 2;
        const long off0 = ((long)(b * SEQ + q0 + wm * 16 + g)) * 1024 + dv;
        const long off1 = ((long)(b * SEQ + q0 + wm * 16 + g + 8)) * 1024 + dv;
        __nv_bfloat162 h2, l2;
        split2(oacc[j][0], oacc[j][1], h2, l2);
        *(__nv_bfloat162*)(oh + off0) = h2;
        *(__nv_bfloat162*)(ol + off0) = l2;
        split2(oacc[j][2], oacc[j][3], h2, l2);
        *(__nv_bfloat162*)(oh + off1) = h2;
        *(__nv_bfloat162*)(ol + off1) = l2;
    }
}

// ---------------- layernorm ----------------
template<bool SPLIT>
__global__ void __launch_bounds__(256) ln_kernel(
    const float* __restrict__ x, const float* __restrict__ gam,
    const float* __restrict__ bet, float* __restrict__ out,
    __nv_bfloat16* __restrict__ ohi, __nv_bfloat16* __restrict__ olo)
{
    __shared__ float red[256];
    const int row = blockIdx.x, tid = threadIdx.x;
    const float4 v = ((const float4*)x)[(long)row * 256 + tid];
    red[tid] = v.x + v.y + v.z + v.w;
    __syncthreads();
#pragma unroll
    for (int off = 128; off; off >>= 1) {
        if (tid < off) red[tid] += red[tid + off];
        __syncthreads();
    }
    const float mu = red[0] * (1.0f / 1024.0f);
    __syncthreads();
    const float dx = v.x - mu, dy = v.y - mu, dz = v.z - mu, dw = v.w - mu;
    red[tid] = dx * dx + dy * dy + dz * dz + dw * dw;
    __syncthreads();
#pragma unroll
    for (int off = 128; off; off >>= 1) {
        if (tid < off) red[tid] += red[tid + off];
        __syncthreads();
    }
    const float var = red[0] * (1.0f / 1024.0f);
    const float rs = rsqrtf(var + 1e-5f);
    const float4 g4 = ((const float4*)gam)[tid];
    const float4 b4 = ((const float4*)bet)[tid];
    float4 o;
    o.x = g4.x * dx * rs + b4.x;
    o.y = g4.y * dy * rs + b4.y;
    o.z = g4.z * dz * rs + b4.z;
    o.w = g4.w * dw * rs + b4.w;
    ((float4*)out)[(long)row * 256 + tid] = o;
    if (SPLIT) {
        const long i = (long)row * 256 + tid;
        __nv_bfloat162 hA, lA, hB, lB;
        split2(o.x, o.y, hA, lA);
        split2(o.z, o.w, hB, lB);
        ((__nv_bfloat162*)ohi)[i*2]   = hA;
        ((__nv_bfloat162*)ohi)[i*2+1] = hB;
        ((__nv_bfloat162*)olo)[i*2]   = lA;
        ((__nv_bfloat162*)olo)[i*2+1] = lB;
    }
}

// ---------------- launch ----------------
extern "C" void kernel_launch(void* const* d_in, const int* in_sizes, int n_in,
                              void* d_out, int out_size) {
    const float* Qin  = (const float*)d_in[0];
    const float* Kin  = (const float*)d_in[1];
    const float* Vin  = (const float*)d_in[2];
    const unsigned char* mask = (const unsigned char*)d_in[3];
    const float* W_q  = (const float*)d_in[4];
    const float* W_k  = (const float*)d_in[5];
    const float* W_v  = (const float*)d_in[6];
    const float* W_o  = (const float*)d_in[7];
    const float* w1   = (const float*)d_in[8];
    const float* b1   = (const float*)d_in[9];
    const float* w2   = (const float*)d_in[10];
    const float* b2   = (const float*)d_in[11];
    const float* ln_g = (const float*)d_in[12];
    const float* ln_b = (const float*)d_in[13];

    float *y_, *x_, *attfb_;
    cudaGetSymbolAddress((void**)&y_, g_y);
    cudaGetSymbolAddress((void**)&x_, g_x);
    cudaGetSymbolAddress((void**)&attfb_, g_att_fb);

    __nv_bfloat16 *ahi, *alo, *qh_, *ql_, *kh_, *kl_, *vh_, *vl_;
    __nv_bfloat16 *wqh, *wql, *wkh, *wkl, *wvh, *wvl, *woh, *wol, *w1h, *w1l, *w2h, *w2l;
    cudaGetSymbolAddress((void**)&ahi, g_ahi);
    cudaGetSymbolAddress((void**)&alo, g_alo);
    cudaGetSymbolAddress((void**)&qh_, g_qh); cudaGetSymbolAddress((void**)&ql_, g_ql);
    cudaGetSymbolAddress((void**)&kh_, g_kh); cudaGetSymbolAddress((void**)&kl_, g_kl);
    cudaGetSymbolAddress((void**)&vh_, g_vh); cudaGetSymbolAddress((void**)&vl_, g_vl);
    cudaGetSymbolAddress((void**)&wqh, g_wqh); cudaGetSymbolAddress((void**)&wql, g_wql);
    cudaGetSymbolAddress((void**)&wkh, g_wkh); cudaGetSymbolAddress((void**)&wkl, g_wkl);
    cudaGetSymbolAddress((void**)&wvh, g_wvh); cudaGetSymbolAddress((void**)&wvl, g_wvl);
    cudaGetSymbolAddress((void**)&woh, g_woh); cudaGetSymbolAddress((void**)&wol, g_wol);
    cudaGetSymbolAddress((void**)&w1h, g_w1h); cudaGetSymbolAddress((void**)&w1l, g_w1l);
    cudaGetSymbolAddress((void**)&w2h, g_w2h); cudaGetSymbolAddress((void**)&w2l, g_w2l);

    __nv_bfloat16* kinh = (__nv_bfloat16*)y_;
    __nv_bfloat16* kinl = kinh + OUT_MAIN;
    __nv_bfloat16* vinh = (__nv_bfloat16*)x_;
    __nv_bfloat16* vinl = vinh + OUT_MAIN;

    float* out = (float*)d_out;
    float* att = (out_size >= (int)(OUT_MAIN + OUT_ATT)) ? (out + OUT_MAIN) : attfb_;

    cudaFuncSetAttribute(mma_gemm<0>, cudaFuncAttributeMaxDynamicSharedMemorySize, GEMM_SMEM);
    cudaFuncSetAttribute(mma_gemm<1>, cudaFuncAttributeMaxDynamicSharedMemorySize, GEMM_SMEM);
    cudaFuncSetAttribute(mma_gemm<2>, cudaFuncAttributeMaxDynamicSharedMemorySize, GEMM_SMEM);
    cudaFuncSetAttribute(mma_gemm<3>, cudaFuncAttributeMaxDynamicSharedMemorySize, GEMM_SMEM);
    cudaFuncSetAttribute(attn2, cudaFuncAttributeMaxDynamicSharedMemorySize, ATTN_SMEM);

    split_transpose4<<<dim3(32, 32, 4), dim3(32, 8)>>>(
        W_q, W_k, W_v, W_o, wqh, wql, wkh, wkl, wvh, wvl, woh, wol);
    splitmulti<<<dim3(DM * DM / 1024, 2), 256>>>(
        w1, w2, nullptr, w1h, w1l, w2h, w2l, nullptr, nullptr);
    splitmulti<<<dim3(MROWS * DM / 1024, 3), 256>>>(
        Qin, Kin, Vin, ahi, alo, kinh, kinl, vinh, vinl);

    const dim3 gG(8, 64), bG(256);
    mma_gemm<0><<<gG, bG, GEMM_SMEM>>>(ahi, alo, wqh, wql, nullptr, nullptr, nullptr, qh_, ql_);
    mma_gemm<0><<<gG, bG, GEMM_SMEM>>>(kinh, kinl, wkh, wkl, nullptr, nullptr, nullptr, kh_, kl_);
    mma_gemm<0><<<gG, bG, GEMM_SMEM>>>(vinh, vinl, wvh, wvl, nullptr, nullptr, nullptr, vh_, vl_);

    attn2<<<dim3(SEQ / 32, BB * NH), 256, ATTN_SMEM>>>(
        qh_, ql_, kh_, kl_, vh_, vl_, mask, att, ahi, alo);

    mma_gemm<1><<<gG, bG, GEMM_SMEM>>>(ahi, alo, woh, wol, y_, Qin, nullptr, nullptr, nullptr);
    ln_kernel<true><<<MROWS, 256>>>(y_, ln_g, ln_b, x_, kh_, kl_);
    mma_gemm<2><<<gG, bG, GEMM_SMEM>>>(kh_, kl_, w1h, w1l, nullptr, nullptr, b1, vh_, vl_);
    mma_gemm<3><<<gG, bG, GEMM_SMEM>>>(vh_, vl_, w2h, w2l, y_, x_, b2, nullptr, nullptr);
    ln_kernel<false><<<MROWS, 256>>>(y_, ln_g, ln_b, out, nullptr, nullptr);
}

// round 15
// speedup vs baseline: 1.0322x; 1.0322x over previous
#include <cuda_runtime.h>
#include <cuda_bf16.h>
#include <math.h>
#include <stdint.h>

// ---------------- problem dims ----------------
#define BB   8
#define SEQ  1024
#define DM   1024
#define NH   16
#define DK   64
#define MROWS (BB*SEQ)
#define OUT_MAIN  (BB*SEQ*DM)
#define OUT_ATT   (BB*NH*SEQ*SEQ)

// ---------------- scratch ----------------
__device__ __align__(128) float g_y[OUT_MAIN];
__device__ __align__(128) float g_x[OUT_MAIN];
__device__ float g_att_fb[OUT_ATT];

__device__ __align__(128) __nv_bfloat16 g_ahi[MROWS*DM];
__device__ __align__(128) __nv_bfloat16 g_alo[MROWS*DM];
__device__ __align__(128) __nv_bfloat16 g_qh[MROWS*DM], g_ql[MROWS*DM];
__device__ __align__(128) __nv_bfloat16 g_kh[MROWS*DM], g_kl[MROWS*DM];
__device__ __align__(128) __nv_bfloat16 g_vh[MROWS*DM], g_vl[MROWS*DM];
__device__ __align__(128) __nv_bfloat16 g_wqh[DM*DM], g_wql[DM*DM];
__device__ __align__(128) __nv_bfloat16 g_wkh[DM*DM], g_wkl[DM*DM];
__device__ __align__(128) __nv_bfloat16 g_wvh[DM*DM], g_wvl[DM*DM];
__device__ __align__(128) __nv_bfloat16 g_woh[DM*DM], g_wol[DM*DM];
__device__ __align__(128) __nv_bfloat16 g_w1h[DM*DM], g_w1l[DM*DM];
__device__ __align__(128) __nv_bfloat16 g_w2h[DM*DM], g_w2l[DM*DM];

// ---------------- helpers ----------------
__device__ __forceinline__ uint32_t cvta_s(const void* p) {
    return (uint32_t)__cvta_generic_to_shared(p);
}
__device__ __forceinline__ void ldsm4(uint32_t r[4], uint32_t a) {
    asm volatile("ldmatrix.sync.aligned.m8n8.x4.shared.b16 {%0,%1,%2,%3}, [%4];"
                 : "=r"(r[0]), "=r"(r[1]), "=r"(r[2]), "=r"(r[3]) : "r"(a));
}
__device__ __forceinline__ void ldsm2(uint32_t r[2], uint32_t a) {
    asm volatile("ldmatrix.sync.aligned.m8n8.x2.shared.b16 {%0,%1}, [%2];"
                 : "=r"(r[0]), "=r"(r[1]) : "r"(a));
}
__device__ __forceinline__ void ldsm2t(uint32_t r[2], uint32_t a) {
    asm volatile("ldmatrix.sync.aligned.m8n8.x2.trans.shared.b16 {%0,%1}, [%2];"
                 : "=r"(r[0]), "=r"(r[1]) : "r"(a));
}
__device__ __forceinline__ void mma_bf16(float c[4], const uint32_t a[4], const uint32_t b[2]) {
    asm volatile(
        "mma.sync.aligned.m16n8k16.row.col.f32.bf16.bf16.f32 "
        "{%0,%1,%2,%3}, {%4,%5,%6,%7}, {%8,%9}, {%0,%1,%2,%3};"
        : "+f"(c[0]), "+f"(c[1]), "+f"(c[2]), "+f"(c[3])
        : "r"(a[0]), "r"(a[1]), "r"(a[2]), "r"(a[3]), "r"(b[0]), "r"(b[1]));
}
__device__ __forceinline__ void cp16(uint32_t d, const void* g) {
    asm volatile("cp.async.cg.shared.global [%0], [%1], 16;" :: "r"(d), "l"(g));
}
#define CP_COMMIT() asm volatile("cp.async.commit_group;" ::: "memory")
#define CP_WAIT1()  asm volatile("cp.async.wait_group 1;" ::: "memory")
#define CP_WAIT0()  asm volatile("cp.async.wait_group 0;" ::: "memory")

// ---------------- fast exp (FMA-only) ----------------
__device__ __forceinline__ float fast_exp(float x) {
    if (x < -87.0f) return 0.0f;
    float t  = x * 1.4426950408889634f;
    float fi = floorf(t);
    float f  = t - fi;
    float p  = 1.5403530e-4f;
    p = fmaf(p, f, 1.3333558e-3f);
    p = fmaf(p, f, 9.6181291e-3f);
    p = fmaf(p, f, 5.5504109e-2f);
    p = fmaf(p, f, 2.4022651e-1f);
    p = fmaf(p, f, 6.9314718e-1f);
    p = fmaf(p, f, 1.0f);
    return __int_as_float(((int)fi + 127) << 23) * p;
}

__device__ __forceinline__ void split2(float v0, float v1, __nv_bfloat162& h2, __nv_bfloat162& l2) {
    h2.x = __float2bfloat16(v0);
    h2.y = __float2bfloat16(v1);
    l2.x = __float2bfloat16(v0 - __bfloat162float(h2.x));
    l2.y = __float2bfloat16(v1 - __bfloat162float(h2.y));
}

// ---------------- batched split ----------------
__global__ void __launch_bounds__(256) splitmulti(
    const float* __restrict__ i0, const float* __restrict__ i1, const float* __restrict__ i2,
    __nv_bfloat16* __restrict__ h0, __nv_bfloat16* __restrict__ l0,
    __nv_bfloat16* __restrict__ h1, __nv_bfloat16* __restrict__ l1,
    __nv_bfloat16* __restrict__ h2p, __nv_bfloat16* __restrict__ l2p)
{
    const float* in; __nv_bfloat16 *hi, *lo;
    if      (blockIdx.y == 0) { in = i0; hi = h0;  lo = l0; }
    else if (blockIdx.y == 1) { in = i1; hi = h1;  lo = l1; }
    else                      { in = i2; hi = h2p; lo = l2p; }
    const int i = blockIdx.x * 256 + threadIdx.x;
    const float4 v = ((const float4*)in)[i];
    __nv_bfloat162 hA, lA, hB, lB;
    split2(v.x, v.y, hA, lA);
    split2(v.z, v.w, hB, lB);
    ((__nv_bfloat162*)hi)[i*2]   = hA;
    ((__nv_bfloat162*)hi)[i*2+1] = hB;
    ((__nv_bfloat162*)lo)[i*2]   = lA;
    ((__nv_bfloat162*)lo)[i*2+1] = lB;
}

__global__ void __launch_bounds__(256) split_transpose4(
    const float* __restrict__ i0, const float* __restrict__ i1,
    const float* __restrict__ i2, const float* __restrict__ i3,
    __nv_bfloat16* __restrict__ h0, __nv_bfloat16* __restrict__ l0,
    __nv_bfloat16* __restrict__ h1, __nv_bfloat16* __restrict__ l1,
    __nv_bfloat16* __restrict__ h2, __nv_bfloat16* __restrict__ l2,
    __nv_bfloat16* __restrict__ h3, __nv_bfloat16* __restrict__ l3)
{
    const float* in; __nv_bfloat16 *hi, *lo;
    if      (blockIdx.z == 0) { in = i0; hi = h0; lo = l0; }
    else if (blockIdx.z == 1) { in = i1; hi = h1; lo = l1; }
    else if (blockIdx.z == 2) { in = i2; hi = h2; lo = l2; }
    else                      { in = i3; hi = h3; lo = l3; }
    __shared__ float t[32][33];
    const int bx = blockIdx.x * 32, by = blockIdx.y * 32;
    const int txx = threadIdx.x, tyy = threadIdx.y;
#pragma unroll
    for (int j = 0; j < 32; j += 8)
        t[tyy + j][txx] = in[(by + tyy + j) * 1024 + bx + txx];
    __syncthreads();
#pragma unroll
    for (int j = 0; j < 32; j += 8) {
        const float v = t[txx][tyy + j];
        __nv_bfloat16 h = __float2bfloat16(v);
        __nv_bfloat16 l = __float2bfloat16(v - __bfloat162float(h));
        const int idx = (bx + tyy + j) * 1024 + by + txx;
        hi[idx] = h;
        lo[idx] = l;
    }
}

// ---------------- HMMA bf16x3 GEMM (k-chunk 32, 3-stage, 1 barrier/chunk) ----------------
#define ROWB 80
#define ASTG 10240
#define STG  40960
#define GEMM_SMEM (3 * STG)

template<int MODE>
__global__ void __launch_bounds__(256) mma_gemm(
    const __nv_bfloat16* __restrict__ Ahi, const __nv_bfloat16* __restrict__ Alo,
    const __nv_bfloat16* __restrict__ Bhi, const __nv_bfloat16* __restrict__ Blo,
    float* __restrict__ C, const float* __restrict__ res, const float* __restrict__ bias,
    __nv_bfloat16* __restrict__ Chi, __nv_bfloat16* __restrict__ Clo)
{
    extern __shared__ __align__(128) char smem[];
    const int tid = threadIdx.x;
    const int lane = tid & 31, w = tid >> 5;
    const int wm = w >> 2, wn = w & 3;
    const int m0 = blockIdx.y * 128, n0 = blockIdx.x * 128;
    const uint32_t sbase = cvta_s(smem);

    float acc[4][4][4];
#pragma unroll
    for (int i = 0; i < 4; i++)
#pragma unroll
        for (int j = 0; j < 4; j++)
#pragma unroll
            for (int k = 0; k < 4; k++) acc[i][j][k] = 0.0f;

    const __nv_bfloat16* gsrc[4] = {Ahi, Alo, Bhi, Blo};

    auto fill = [&](int buf, int kc) {
        const int k0 = kc * 32;
        const uint32_t dst0 = sbase + buf * STG;
#pragma unroll
        for (int i = 0; i < 8; i++) {
            const int idx = i * 256 + tid;
            const int arr = idx >> 9;
            const int within = idx & 511;
            const int row = within >> 2, seg = within & 3;
            const int grow = (arr < 2 ? m0 : n0) + row;
            const __nv_bfloat16* g = gsrc[arr] + (long)grow * 1024 + k0 + seg * 8;
            cp16(dst0 + arr * ASTG + row * ROWB + seg * 16, g);
        }
        CP_COMMIT();
    };

    fill(0, 0);
    fill(1, 1);
    int buf = 0;
    for (int c = 0; c < 32; c++) {
        if (c < 31) CP_WAIT1(); else CP_WAIT0();
        __syncthreads();
        if (c + 2 < 32) {
            int nb = buf + 2; if (nb >= 3) nb -= 3;
            fill(nb, c + 2);
        }

        const uint32_t sb = sbase + buf * STG;
#pragma unroll
        for (int s = 0; s < 2; s++) {
            uint32_t ah[4][4], al[4][4], bh[4][2], bl[4][2];
            const int acol = (s * 16 + (lane >> 4) * 8) * 2;
            const int arow = lane & 15;
#pragma unroll
            for (int mt = 0; mt < 4; mt++) {
                const uint32_t ao = sb + (wm * 64 + mt * 16 + arow) * ROWB + acol;
                ldsm4(ah[mt], ao);
                ldsm4(al[mt], ao + ASTG);
            }
            const int le = lane & 15;
            const int bcol = (s * 16 + ((le >> 3) & 1) * 8) * 2;
            const int brow = le & 7;
#pragma unroll
            for (int nt = 0; nt < 4; nt++) {
                const uint32_t bo = sb + 2 * ASTG + (wn * 32 + nt * 8 + brow) * ROWB + bcol;
                ldsm2(bh[nt], bo);
                ldsm2(bl[nt], bo + ASTG);
            }
#pragma unroll
            for (int mt = 0; mt < 4; mt++)
#pragma unroll
                for (int nt = 0; nt < 4; nt++) {
                    mma_bf16(acc[mt][nt], ah[mt], bh[nt]);
                    mma_bf16(acc[mt][nt], ah[mt], bl[nt]);
                    mma_bf16(acc[mt][nt], al[mt], bh[nt]);
                }
        }
        if (++buf == 3) buf = 0;
    }

    // ---- epilogue ----
    const int g = lane >> 2, t4 = lane & 3;
#pragma unroll
    for (int mt = 0; mt < 4; mt++) {
#pragma unroll
        for (int half = 0; half < 2; half++) {
            const int m = m0 + wm * 64 + mt * 16 + g + half * 8;
#pragma unroll
            for (int nt = 0; nt < 4; nt++) {
                const int n = n0 + wn * 32 + nt * 8 + t4 * 2;
                float v0 = acc[mt][nt][half * 2 + 0];
                float v1 = acc[mt][nt][half * 2 + 1];
                if (MODE == 0) {
                    const int b = m >> 10, s = m & 1023, h = n >> 6, d = n & 63;
                    const long off = ((long)((b * 16 + h) * 1024 + s)) * 64 + d;
                    __nv_bfloat162 h2, l2;
                    split2(v0, v1, h2, l2);
                    *(__nv_bfloat162*)(Chi + off) = h2;
                    *(__nv_bfloat162*)(Clo + off) = l2;
                } else if (MODE == 1) {
                    const float2 r2 = *(const float2*)&res[(long)m * 1024 + n];
                    float2 o; o.x = v0 + r2.x; o.y = v1 + r2.y;
                    *(float2*)&C[(long)m * 1024 + n] = o;
                } else if (MODE == 2) {
                    const float2 bi = *(const float2*)&bias[n];
                    const float is2 = 0.70710678118654752f;
                    float x0 = v0 + bi.x, x1 = v1 + bi.y;
                    float g0 = 0.5f * x0 * (1.0f + erff(x0 * is2));
                    float g1 = 0.5f * x1 * (1.0f + erff(x1 * is2));
                    const long off = (long)m * 1024 + n;
                    __nv_bfloat162 h2, l2;
                    split2(g0, g1, h2, l2);
                    *(__nv_bfloat162*)(Chi + off) = h2;
                    *(__nv_bfloat162*)(Clo + off) = l2;
                } else {
                    const float2 bi = *(const float2*)&bias[n];
                    const float2 r2 = *(const float2*)&res[(long)m * 1024 + n];
                    float2 o; o.x = v0 + bi.x + r2.x; o.y = v1 + bi.y + r2.y;
                    *(float2*)&C[(long)m * 1024 + n] = o;
                }
            }
        }
    }
}

// ---------------- HMMA attention, 32 q-rows/block, 3-stage KV, packed P ----------------
#define AT_QH 0
#define AT_QL 4608
#define AT_KV 9216
#define AT_KVS 18432
#define AT_SS 64512
#define SSPW 1034
#define ATTN_SMEM (AT_SS + 32 * SSPW * 4)   // 196864

__global__ void __launch_bounds__(256) attn2(
    const __nv_bfloat16* __restrict__ qh, const __nv_bfloat16* __restrict__ ql,
    const __nv_bfloat16* __restrict__ kh, const __nv_bfloat16* __restrict__ kl,
    const __nv_bfloat16* __restrict__ vh, const __nv_bfloat16* __restrict__ vl,
    const unsigned char* __restrict__ mask,
    float* __restrict__ att,
    __nv_bfloat16* __restrict__ oh, __nv_bfloat16* __restrict__ ol)
{
    extern __shared__ __align__(128) char sm[];
    __shared__ int s_any;
    const uint32_t sbase = cvta_s(sm);
    const int tid = threadIdx.x;
    const int lane = tid & 31, w = tid >> 5;
    const int wm = w >> 2, wn = w & 3;
    const int qt = blockIdx.x, bh = blockIdx.y;
    const int b = bh >> 4, h = bh & 15;
    const int q0 = qt * 32;
    const long base = (long)bh * SEQ * 64;
    const float scale = 1.0f / (8.0f + 1e-6f);
    float* Ss = (float*)(sm + AT_SS);

    auto fillKV = [&](const __nv_bfloat16* phi_, const __nv_bfloat16* plo_, int buf, int kt) {
#pragma unroll
        for (int i = 0; i < 4; i++) {
            const int idx = i * 256 + tid;
            const int arr = idx >> 9;
            const int wi = idx & 511;
            const int row = wi >> 3, seg = wi & 7;
            const __nv_bfloat16* g = (arr ? plo_ : phi_) + base + (long)(kt * 64 + row) * 64 + seg * 8;
            cp16(sbase + AT_KV + buf * AT_KVS + arr * 9216 + row * 144 + seg * 16, g);
        }
        CP_COMMIT();
    };

    // Q hi/lo (joins K0's commit group)
#pragma unroll
    for (int i = 0; i < 2; i++) {
        const int idx = i * 256 + tid;
        const int arr = idx >> 8;
        const int wi = idx & 255;
        const int row = wi >> 3, seg = wi & 7;
        const __nv_bfloat16* g = (arr ? ql : qh) + base + (long)(q0 + row) * 64 + seg * 8;
        cp16(sbase + (arr ? AT_QL : AT_QH) + row * 144 + seg * 16, g);
    }
    if (tid == 0) s_any = 0;

    const int kt_max = (q0 + 31) >> 6;
    const int NC = kt_max + 1;

    fillKV(kh, kl, 0, 0);
    if (NC > 1) fillKV(kh, kl, 1, 1);

    if (tid < 32 && mask[b * SEQ + q0 + tid]) s_any = 1;

    // ---- phase 1: scores (1 barrier/chunk, fills 2 ahead) ----
    uint32_t ah[4][4], al[4][4];
    int buf = 0;
    for (int kt = 0; kt < NC; kt++) {
        if (kt < NC - 1) CP_WAIT1(); else CP_WAIT0();
        __syncthreads();
        if (kt + 2 < NC) {
            int nb = buf + 2; if (nb >= 3) nb -= 3;
            fillKV(kh, kl, nb, kt + 2);
        }
        if (kt == 0) {
#pragma unroll
            for (int s = 0; s < 4; s++) {
                const uint32_t qa = sbase + (wm * 16 + (lane & 15)) * 144 + s * 32 + (lane >> 4) * 16;
                ldsm4(ah[s], qa + AT_QH);
                ldsm4(al[s], qa + AT_QL);
            }
        }
        const uint32_t khb = sbase + AT_KV + buf * AT_KVS;
        const int le = lane & 15;
#pragma unroll
        for (int j = 0; j < 2; j++) {
            float c[4] = {0, 0, 0, 0};
#pragma unroll
            for (int s = 0; s < 4; s++) {
                uint32_t bhr[2], blr[2];
                const uint32_t ka = khb + (wn * 16 + j * 8 + (le & 7)) * 144 + s * 32 + ((le >> 3) & 1) * 16;
                ldsm2(bhr, ka);
                ldsm2(blr, ka + 9216);
                mma_bf16(c, ah[s], bhr);
                mma_bf16(c, ah[s], blr);
                mma_bf16(c, al[s], bhr);
            }
            const int r = wm * 16 + (lane >> 2);
            const int col = kt * 64 + wn * 16 + j * 8 + (lane & 3) * 2;
            float2 st0; st0.x = c[0] * scale; st0.y = c[1] * scale;
            float2 st1; st1.x = c[2] * scale; st1.y = c[3] * scale;
            *(float2*)(Ss + r * SSPW + col) = st0;
            *(float2*)(Ss + (r + 8) * SSPW + col) = st1;
        }
        if (++buf == 3) buf = 0;
    }
    __syncthreads();

    const int kt_end = s_any ? (SEQ / 64 - 1) : kt_max;
    const int AVNC = kt_end + 1;

    // prefetch V chunks 0,1 under softmax
    fillKV(vh, vl, 0, 0);
    if (AVNC > 1) fillKV(vh, vl, 1, 1);

    // ---- phase 2: softmax (8 threads/row), pack p -> (bf16 hi, bf16 lo) in place ----
    {
        const int r = tid >> 3, tc = tid & 7;
        const int qg = q0 + r;
        const int limit = qg;
        const bool rmask = mask[b * SEQ + qg] != 0;
        float* srow = Ss + r * SSPW;

        float mx = -3.4e38f;
#pragma unroll 4
        for (int j = 0; j < 128; j++) {
            const int k = tc + (j << 3);
            if (k <= limit) mx = fmaxf(mx, srow[k]);
        }
#pragma unroll
        for (int off = 4; off; off >>= 1)
            mx = fmaxf(mx, __shfl_xor_sync(0xffffffffu, mx, off, 8));

        float l = 0.0f;
#pragma unroll 4
        for (int j = 0; j < 128; j++) {
            const int k = tc + (j << 3);
            if (k <= limit) {
                const float e = fast_exp(srow[k] - mx);
                srow[k] = e;
                l += e;
            }
        }
#pragma unroll
        for (int off = 4; off; off >>= 1)
            l += __shfl_xor_sync(0xffffffffu, l, off, 8);
        const float inv = 1.0f / l;
        const float invS = 1.0f / (float)SEQ;

        float* attrow = att + ((long)bh * SEQ + qg) * SEQ;
        uint32_t* prow = (uint32_t*)srow;
#pragma unroll 4
        for (int j = 0; j < 128; j++) {
            const int k = tc + (j << 3);
            float p;
            if (rmask)           p = invS;
            else if (k <= limit) p = srow[k] * inv;
            else                 p = 0.0f;
            attrow[k] = p;
            const __nv_bfloat16 phi = __float2bfloat16(p);
            const __nv_bfloat16 plo = __float2bfloat16(p - __bfloat162float(phi));
            prow[k] = (uint32_t)__bfloat16_as_ushort(phi) |
                      ((uint32_t)__bfloat16_as_ushort(plo) << 16);
        }
    }
    __syncthreads();

    // ---- phase 3: AV (1 barrier/chunk) ----
    float oacc[2][4];
#pragma unroll
    for (int j = 0; j < 2; j++)
#pragma unroll
        for (int k = 0; k < 4; k++) oacc[j][k] = 0.0f;

    const int g = lane >> 2, t4 = lane & 3;
    buf = 0;
    for (int kt = 0; kt < AVNC; kt++) {
        if (kt < AVNC - 1) CP_WAIT1(); else CP_WAIT0();
        __syncthreads();
        if (kt + 2 < AVNC) {
            int nb = buf + 2; if (nb >= 3) nb -= 3;
            fillKV(vh, vl, nb, kt + 2);
        }
        const uint32_t vbh = sbase + AT_KV + buf * AT_KVS;
#pragma unroll
        for (int s = 0; s < 4; s++) {
            uint32_t pa[4], pb[4];
#pragma unroll
            for (int kk = 0; kk < 2; kk++) {
#pragma unroll
                for (int mi = 0; mi < 2; mi++) {
                    const int row = wm * 16 + g + mi * 8;
                    const int col = kt * 64 + s * 16 + kk * 8 + t4 * 2;
                    const uint2 ww = *(const uint2*)(Ss + row * SSPW + col);
                    const int fi = kk * 2 + mi;
                    pa[fi] = __byte_perm(ww.x, ww.y, 0x5410);
                    pb[fi] = __byte_perm(ww.x, ww.y, 0x7632);
                }
            }
#pragma unroll
            for (int j = 0; j < 2; j++) {
                uint32_t vvh[2], vvl[2];
                const uint32_t va = vbh + (s * 16 + (lane & 15)) * 144 + wn * 32 + j * 16;
                ldsm2t(vvh, va);
                ldsm2t(vvl, va + 9216);
                mma_bf16(oacc[j], pa, vvh);
                mma_bf16(oacc[j], pa, vvl);
                mma_bf16(oacc[j], pb, vvh);
            }
        }
        if (++buf == 3) buf = 0;
    }

    // epilogue: bf16 hi/lo direct to [M][1024]
#pragma unroll
    for (int j = 0; j < 2; j++) {
        const int dv = h * 64 + wn * 16 + j * 8 + t4 * 2;
        const long off0 = ((long)(b * SEQ + q0 + wm * 16 + g)) * 1024 + dv;
        const long off1 = ((long)(b * SEQ + q0 + wm * 16 + g + 8)) * 1024 + dv;
        __nv_bfloat162 h2, l2;
        split2(oacc[j][0], oacc[j][1], h2, l2);
        *(__nv_bfloat162*)(oh + off0) = h2;
        *(__nv_bfloat162*)(ol + off0) = l2;
        split2(oacc[j][2], oacc[j][3], h2, l2);
        *(__nv_bfloat162*)(oh + off1) = h2;
        *(__nv_bfloat162*)(ol + off1) = l2;
    }
}

// ---------------- layernorm ----------------
template<bool SPLIT>
__global__ void __launch_bounds__(256) ln_kernel(
    const float* __restrict__ x, const float* __restrict__ gam,
    const float* __restrict__ bet, float* __restrict__ out,
    __nv_bfloat16* __restrict__ ohi, __nv_bfloat16* __restrict__ olo)
{
    __shared__ float red[256];
    const int row = blockIdx.x, tid = threadIdx.x;
    const float4 v = ((const float4*)x)[(long)row * 256 + tid];
    red[tid] = v.x + v.y + v.z + v.w;
    __syncthreads();
#pragma unroll
    for (int off = 128; off; off >>= 1) {
        if (tid < off) red[tid] += red[tid + off];
        __syncthreads();
    }
    const float mu = red[0] * (1.0f / 1024.0f);
    __syncthreads();
    const float dx = v.x - mu, dy = v.y - mu, dz = v.z - mu, dw = v.w - mu;
    red[tid] = dx * dx + dy * dy + dz * dz + dw * dw;
    __syncthreads();
#pragma unroll
    for (int off = 128; off; off >>= 1) {
        if (tid < off) red[tid] += red[tid + off];
        __syncthreads();
    }
    const float var = red[0] * (1.0f / 1024.0f);
    const float rs = rsqrtf(var + 1e-5f);
    const float4 g4 = ((const float4*)gam)[tid];
    const float4 b4 = ((const float4*)bet)[tid];
    float4 o;
    o.x = g4.x * dx * rs + b4.x;
    o.y = g4.y * dy * rs + b4.y;
    o.z = g4.z * dz * rs + b4.z;
    o.w = g4.w * dw * rs + b4.w;
    ((float4*)out)[(long)row * 256 + tid] = o;
    if (SPLIT) {
        const long i = (long)row * 256 + tid;
        __nv_bfloat162 hA, lA, hB, lB;
        split2(o.x, o.y, hA, lA);
        split2(o.z, o.w, hB, lB);
        ((__nv_bfloat162*)ohi)[i*2]   = hA;
        ((__nv_bfloat162*)ohi)[i*2+1] = hB;
        ((__nv_bfloat162*)olo)[i*2]   = lA;
        ((__nv_bfloat162*)olo)[i*2+1] = lB;
    }
}

// ---------------- launch ----------------
extern "C" void kernel_launch(void* const* d_in, const int* in_sizes, int n_in,
                              void* d_out, int out_size) {
    const float* Qin  = (const float*)d_in[0];
    const float* Kin  = (const float*)d_in[1];
    const float* Vin  = (const float*)d_in[2];
    const unsigned char* mask = (const unsigned char*)d_in[3];
    const float* W_q  = (const float*)d_in[4];
    const float* W_k  = (const float*)d_in[5];
    const float* W_v  = (const float*)d_in[6];
    const float* W_o  = (const float*)d_in[7];
    const float* w1   = (const float*)d_in[8];
    const float* b1   = (const float*)d_in[9];
    const float* w2   = (const float*)d_in[10];
    const float* b2   = (const float*)d_in[11];
    const float* ln_g = (const float*)d_in[12];
    const float* ln_b = (const float*)d_in[13];

    float *y_, *x_, *attfb_;
    cudaGetSymbolAddress((void**)&y_, g_y);
    cudaGetSymbolAddress((void**)&x_, g_x);
    cudaGetSymbolAddress((void**)&attfb_, g_att_fb);

    __nv_bfloat16 *ahi, *alo, *qh_, *ql_, *kh_, *kl_, *vh_, *vl_;
    __nv_bfloat16 *wqh, *wql, *wkh, *wkl, *wvh, *wvl, *woh, *wol, *w1h, *w1l, *w2h, *w2l;
    cudaGetSymbolAddress((void**)&ahi, g_ahi);
    cudaGetSymbolAddress((void**)&alo, g_alo);
    cudaGetSymbolAddress((void**)&qh_, g_qh); cudaGetSymbolAddress((void**)&ql_, g_ql);
    cudaGetSymbolAddress((void**)&kh_, g_kh); cudaGetSymbolAddress((void**)&kl_, g_kl);
    cudaGetSymbolAddress((void**)&vh_, g_vh); cudaGetSymbolAddress((void**)&vl_, g_vl);
    cudaGetSymbolAddress((void**)&wqh, g_wqh); cudaGetSymbolAddress((void**)&wql, g_wql);
    cudaGetSymbolAddress((void**)&wkh, g_wkh); cudaGetSymbolAddress((void**)&wkl, g_wkl);
    cudaGetSymbolAddress((void**)&wvh, g_wvh); cudaGetSymbolAddress((void**)&wvl, g_wvl);
    cudaGetSymbolAddress((void**)&woh, g_woh); cudaGetSymbolAddress((void**)&wol, g_wol);
    cudaGetSymbolAddress((void**)&w1h, g_w1h); cudaGetSymbolAddress((void**)&w1l, g_w1l);
    cudaGetSymbolAddress((void**)&w2h, g_w2h); cudaGetSymbolAddress((void**)&w2l, g_w2l);

    __nv_bfloat16* kinh = (__nv_bfloat16*)y_;
    __nv_bfloat16* kinl = kinh + OUT_MAIN;
    __nv_bfloat16* vinh = (__nv_bfloat16*)x_;
    __nv_bfloat16* vinl = vinh + OUT_MAIN;

    float* out = (float*)d_out;
    float* att = (out_size >= (int)(OUT_MAIN + OUT_ATT)) ? (out + OUT_MAIN) : attfb_;

    cudaFuncSetAttribute(mma_gemm<0>, cudaFuncAttributeMaxDynamicSharedMemorySize, GEMM_SMEM);
    cudaFuncSetAttribute(mma_gemm<1>, cudaFuncAttributeMaxDynamicSharedMemorySize, GEMM_SMEM);
    cudaFuncSetAttribute(mma_gemm<2>, cudaFuncAttributeMaxDynamicSharedMemorySize, GEMM_SMEM);
    cudaFuncSetAttribute(mma_gemm<3>, cudaFuncAttributeMaxDynamicSharedMemorySize, GEMM_SMEM);
    cudaFuncSetAttribute(attn2, cudaFuncAttributeMaxDynamicSharedMemorySize, ATTN_SMEM);

    split_transpose4<<<dim3(32, 32, 4), dim3(32, 8)>>>(
        W_q, W_k, W_v, W_o, wqh, wql, wkh, wkl, wvh, wvl, woh, wol);
    splitmulti<<<dim3(DM * DM / 1024, 2), 256>>>(
        w1, w2, nullptr, w1h, w1l, w2h, w2l, nullptr, nullptr);
    splitmulti<<<dim3(MROWS * DM / 1024, 3), 256>>>(
        Qin, Kin, Vin, ahi, alo, kinh, kinl, vinh, vinl);

    const dim3 gG(8, 64), bG(256);
    mma_gemm<0><<<gG, bG, GEMM_SMEM>>>(ahi, alo, wqh, wql, nullptr, nullptr, nullptr, qh_, ql_);
    mma_gemm<0><<<gG, bG, GEMM_SMEM>>>(kinh, kinl, wkh, wkl, nullptr, nullptr, nullptr, kh_, kl_);
    mma_gemm<0><<<gG, bG, GEMM_SMEM>>>(vinh, vinl, wvh, wvl, nullptr, nullptr, nullptr, vh_, vl_);

    attn2<<<dim3(SEQ / 32, BB * NH), 256, ATTN_SMEM>>>(
        qh_, ql_, kh_, kl_, vh_, vl_, mask, att, ahi, alo);

    mma_gemm<1><<<gG, bG, GEMM_SMEM>>>(ahi, alo, woh, wol, y_, Qin, nullptr, nullptr, nullptr);
    ln_kernel<true><<<MROWS, 256>>>(y_, ln_g, ln_b, x_, kh_, kl_);
    mma_gemm<2><<<gG, bG, GEMM_SMEM>>>(kh_, kl_, w1h, w1l, nullptr, nullptr, b1, vh_, vl_);
    mma_gemm<3><<<gG, bG, GEMM_SMEM>>>(vh_, vl_, w2h, w2l, y_, x_, b2, nullptr, nullptr);
    ln_kernel<false><<<MROWS, 256>>>(y_, ln_g, ln_b, out, nullptr, nullptr);
}

// round 16
// speedup vs baseline: 1.1351x; 1.0996x over previous
#include <cuda_runtime.h>
#include <cuda_bf16.h>
#include <math.h>
#include <stdint.h>

// ---------------- problem dims ----------------
#define BB   8
#define SEQ  1024
#define DM   1024
#define NH   16
#define DK   64
#define MROWS (BB*SEQ)
#define OUT_MAIN  (BB*SEQ*DM)
#define OUT_ATT   (BB*NH*SEQ*SEQ)

// ---------------- scratch ----------------
__device__ __align__(128) float g_y[OUT_MAIN];
__device__ __align__(128) float g_x[OUT_MAIN];
__device__ float g_att_fb[OUT_ATT];

__device__ __align__(128) __nv_bfloat16 g_ahi[MROWS*DM];
__device__ __align__(128) __nv_bfloat16 g_alo[MROWS*DM];
__device__ __align__(128) __nv_bfloat16 g_qh[MROWS*DM], g_ql[MROWS*DM];
__device__ __align__(128) __nv_bfloat16 g_kh[MROWS*DM], g_kl[MROWS*DM];
__device__ __align__(128) __nv_bfloat16 g_vh[MROWS*DM], g_vl[MROWS*DM];
__device__ __align__(128) __nv_bfloat16 g_wqh[DM*DM], g_wql[DM*DM];
__device__ __align__(128) __nv_bfloat16 g_wkh[DM*DM], g_wkl[DM*DM];
__device__ __align__(128) __nv_bfloat16 g_wvh[DM*DM], g_wvl[DM*DM];
__device__ __align__(128) __nv_bfloat16 g_woh[DM*DM], g_wol[DM*DM];
__device__ __align__(128) __nv_bfloat16 g_w1h[DM*DM], g_w1l[DM*DM];
__device__ __align__(128) __nv_bfloat16 g_w2h[DM*DM], g_w2l[DM*DM];

// ---------------- helpers ----------------
__device__ __forceinline__ uint32_t cvta_s(const void* p) {
    return (uint32_t)__cvta_generic_to_shared(p);
}
__device__ __forceinline__ void ldsm4(uint32_t r[4], uint32_t a) {
    asm volatile("ldmatrix.sync.aligned.m8n8.x4.shared.b16 {%0,%1,%2,%3}, [%4];"
                 : "=r"(r[0]), "=r"(r[1]), "=r"(r[2]), "=r"(r[3]) : "r"(a));
}
__device__ __forceinline__ void ldsm2(uint32_t r[2], uint32_t a) {
    asm volatile("ldmatrix.sync.aligned.m8n8.x2.shared.b16 {%0,%1}, [%2];"
                 : "=r"(r[0]), "=r"(r[1]) : "r"(a));
}
__device__ __forceinline__ void ldsm2t(uint32_t r[2], uint32_t a) {
    asm volatile("ldmatrix.sync.aligned.m8n8.x2.trans.shared.b16 {%0,%1}, [%2];"
                 : "=r"(r[0]), "=r"(r[1]) : "r"(a));
}
__device__ __forceinline__ void mma_bf16(float c[4], const uint32_t a[4], const uint32_t b[2]) {
    asm volatile(
        "mma.sync.aligned.m16n8k16.row.col.f32.bf16.bf16.f32 "
        "{%0,%1,%2,%3}, {%4,%5,%6,%7}, {%8,%9}, {%0,%1,%2,%3};"
        : "+f"(c[0]), "+f"(c[1]), "+f"(c[2]), "+f"(c[3])
        : "r"(a[0]), "r"(a[1]), "r"(a[2]), "r"(a[3]), "r"(b[0]), "r"(b[1]));
}
__device__ __forceinline__ void cp16(uint32_t d, const void* g) {
    asm volatile("cp.async.cg.shared.global [%0], [%1], 16;" :: "r"(d), "l"(g));
}
#define CP_COMMIT() asm volatile("cp.async.commit_group;" ::: "memory")
#define CP_WAIT1()  asm volatile("cp.async.wait_group 1;" ::: "memory")
#define CP_WAIT0()  asm volatile("cp.async.wait_group 0;" ::: "memory")

// ---------------- fast exp (FMA-only) ----------------
__device__ __forceinline__ float fast_exp(float x) {
    if (x < -87.0f) return 0.0f;
    float t  = x * 1.4426950408889634f;
    float fi = floorf(t);
    float f  = t - fi;
    float p  = 1.5403530e-4f;
    p = fmaf(p, f, 1.3333558e-3f);
    p = fmaf(p, f, 9.6181291e-3f);
    p = fmaf(p, f, 5.5504109e-2f);
    p = fmaf(p, f, 2.4022651e-1f);
    p = fmaf(p, f, 6.9314718e-1f);
    p = fmaf(p, f, 1.0f);
    return __int_as_float(((int)fi + 127) << 23) * p;
}

__device__ __forceinline__ void split2(float v0, float v1, __nv_bfloat162& h2, __nv_bfloat162& l2) {
    h2.x = __float2bfloat16(v0);
    h2.y = __float2bfloat16(v1);
    l2.x = __float2bfloat16(v0 - __bfloat162float(h2.x));
    l2.y = __float2bfloat16(v1 - __bfloat162float(h2.y));
}

// ---------------- batched split ----------------
__global__ void __launch_bounds__(256) splitmulti(
    const float* __restrict__ i0, const float* __restrict__ i1, const float* __restrict__ i2,
    __nv_bfloat16* __restrict__ h0, __nv_bfloat16* __restrict__ l0,
    __nv_bfloat16* __restrict__ h1, __nv_bfloat16* __restrict__ l1,
    __nv_bfloat16* __restrict__ h2p, __nv_bfloat16* __restrict__ l2p)
{
    const float* in; __nv_bfloat16 *hi, *lo;
    if      (blockIdx.y == 0) { in = i0; hi = h0;  lo = l0; }
    else if (blockIdx.y == 1) { in = i1; hi = h1;  lo = l1; }
    else                      { in = i2; hi = h2p; lo = l2p; }
    const int i = blockIdx.x * 256 + threadIdx.x;
    const float4 v = ((const float4*)in)[i];
    __nv_bfloat162 hA, lA, hB, lB;
    split2(v.x, v.y, hA, lA);
    split2(v.z, v.w, hB, lB);
    ((__nv_bfloat162*)hi)[i*2]   = hA;
    ((__nv_bfloat162*)hi)[i*2+1] = hB;
    ((__nv_bfloat162*)lo)[i*2]   = lA;
    ((__nv_bfloat162*)lo)[i*2+1] = lB;
}

__global__ void __launch_bounds__(256) split_transpose4(
    const float* __restrict__ i0, const float* __restrict__ i1,
    const float* __restrict__ i2, const float* __restrict__ i3,
    __nv_bfloat16* __restrict__ h0, __nv_bfloat16* __restrict__ l0,
    __nv_bfloat16* __restrict__ h1, __nv_bfloat16* __restrict__ l1,
    __nv_bfloat16* __restrict__ h2, __nv_bfloat16* __restrict__ l2,
    __nv_bfloat16* __restrict__ h3, __nv_bfloat16* __restrict__ l3)
{
    const float* in; __nv_bfloat16 *hi, *lo;
    if      (blockIdx.z == 0) { in = i0; hi = h0; lo = l0; }
    else if (blockIdx.z == 1) { in = i1; hi = h1; lo = l1; }
    else if (blockIdx.z == 2) { in = i2; hi = h2; lo = l2; }
    else                      { in = i3; hi = h3; lo = l3; }
    __shared__ float t[32][33];
    const int bx = blockIdx.x * 32, by = blockIdx.y * 32;
    const int txx = threadIdx.x, tyy = threadIdx.y;
#pragma unroll
    for (int j = 0; j < 32; j += 8)
        t[tyy + j][txx] = in[(by + tyy + j) * 1024 + bx + txx];
    __syncthreads();
#pragma unroll
    for (int j = 0; j < 32; j += 8) {
        const float v = t[txx][tyy + j];
        __nv_bfloat16 h = __float2bfloat16(v);
        __nv_bfloat16 l = __float2bfloat16(v - __bfloat162float(h));
        const int idx = (bx + tyy + j) * 1024 + by + txx;
        hi[idx] = h;
        lo[idx] = l;
    }
}

// ---------------- HMMA bf16x3 GEMM (k-chunk 32, 2-stage, 2 CTAs/SM) ----------------
#define ROWB 80
#define ASTG 10240
#define STG  40960
#define GEMM_SMEM (2 * STG)

template<int MODE>
__global__ void __launch_bounds__(256, 2) mma_gemm(
    const __nv_bfloat16* __restrict__ Ahi, const __nv_bfloat16* __restrict__ Alo,
    const __nv_bfloat16* __restrict__ Bhi, const __nv_bfloat16* __restrict__ Blo,
    float* __restrict__ C, const float* __restrict__ res, const float* __restrict__ bias,
    __nv_bfloat16* __restrict__ Chi, __nv_bfloat16* __restrict__ Clo)
{
    extern __shared__ __align__(128) char smem[];
    const int tid = threadIdx.x;
    const int lane = tid & 31, w = tid >> 5;
    const int wm = w >> 2, wn = w & 3;
    const int m0 = blockIdx.y * 128, n0 = blockIdx.x * 128;
    const uint32_t sbase = cvta_s(smem);

    float acc[4][4][4];
#pragma unroll
    for (int i = 0; i < 4; i++)
#pragma unroll
        for (int j = 0; j < 4; j++)
#pragma unroll
            for (int k = 0; k < 4; k++) acc[i][j][k] = 0.0f;

    const __nv_bfloat16* gsrc[4] = {Ahi, Alo, Bhi, Blo};

    auto fill = [&](int buf, int kc) {
        const int k0 = kc * 32;
        const uint32_t dst0 = sbase + buf * STG;
#pragma unroll
        for (int i = 0; i < 8; i++) {
            const int idx = i * 256 + tid;
            const int arr = idx >> 9;
            const int within = idx & 511;
            const int row = within >> 2, seg = within & 3;
            const int grow = (arr < 2 ? m0 : n0) + row;
            const __nv_bfloat16* g = gsrc[arr] + (long)grow * 1024 + k0 + seg * 8;
            cp16(dst0 + arr * ASTG + row * ROWB + seg * 16, g);
        }
        CP_COMMIT();
    };

    fill(0, 0);
    for (int c = 0; c < 32; c++) {
        const int buf = c & 1;
        if (c + 1 < 32) {
            fill(buf ^ 1, c + 1);
            CP_WAIT1();
        } else {
            CP_WAIT0();
        }
        __syncthreads();

        const uint32_t sb = sbase + buf * STG;
#pragma unroll
        for (int s = 0; s < 2; s++) {
            uint32_t ah[4][4], al[4][4], bh[4][2], bl[4][2];
            const int acol = (s * 16 + (lane >> 4) * 8) * 2;
            const int arow = lane & 15;
#pragma unroll
            for (int mt = 0; mt < 4; mt++) {
                const uint32_t ao = sb + (wm * 64 + mt * 16 + arow) * ROWB + acol;
                ldsm4(ah[mt], ao);
                ldsm4(al[mt], ao + ASTG);
            }
            const int le = lane & 15;
            const int bcol = (s * 16 + ((le >> 3) & 1) * 8) * 2;
            const int brow = le & 7;
#pragma unroll
            for (int nt = 0; nt < 4; nt++) {
                const uint32_t bo = sb + 2 * ASTG + (wn * 32 + nt * 8 + brow) * ROWB + bcol;
                ldsm2(bh[nt], bo);
                ldsm2(bl[nt], bo + ASTG);
            }
#pragma unroll
            for (int mt = 0; mt < 4; mt++)
#pragma unroll
                for (int nt = 0; nt < 4; nt++) {
                    mma_bf16(acc[mt][nt], ah[mt], bh[nt]);
                    mma_bf16(acc[mt][nt], ah[mt], bl[nt]);
                    mma_bf16(acc[mt][nt], al[mt], bh[nt]);
                }
        }
        __syncthreads();
    }

    // ---- epilogue ----
    const int g = lane >> 2, t4 = lane & 3;
#pragma unroll
    for (int mt = 0; mt < 4; mt++) {
#pragma unroll
        for (int half = 0; half < 2; half++) {
            const int m = m0 + wm * 64 + mt * 16 + g + half * 8;
#pragma unroll
            for (int nt = 0; nt < 4; nt++) {
                const int n = n0 + wn * 32 + nt * 8 + t4 * 2;
                float v0 = acc[mt][nt][half * 2 + 0];
                float v1 = acc[mt][nt][half * 2 + 1];
                if (MODE == 0) {
                    const int b = m >> 10, s = m & 1023, h = n >> 6, d = n & 63;
                    const long off = ((long)((b * 16 + h) * 1024 + s)) * 64 + d;
                    __nv_bfloat162 h2, l2;
                    split2(v0, v1, h2, l2);
                    *(__nv_bfloat162*)(Chi + off) = h2;
                    *(__nv_bfloat162*)(Clo + off) = l2;
                } else if (MODE == 1) {
                    const float2 r2 = *(const float2*)&res[(long)m * 1024 + n];
                    float2 o; o.x = v0 + r2.x; o.y = v1 + r2.y;
                    *(float2*)&C[(long)m * 1024 + n] = o;
                } else if (MODE == 2) {
                    const float2 bi = *(const float2*)&bias[n];
                    const float is2 = 0.70710678118654752f;
                    float x0 = v0 + bi.x, x1 = v1 + bi.y;
                    float g0 = 0.5f * x0 * (1.0f + erff(x0 * is2));
                    float g1 = 0.5f * x1 * (1.0f + erff(x1 * is2));
                    const long off = (long)m * 1024 + n;
                    __nv_bfloat162 h2, l2;
                    split2(g0, g1, h2, l2);
                    *(__nv_bfloat162*)(Chi + off) = h2;
                    *(__nv_bfloat162*)(Clo + off) = l2;
                } else {
                    const float2 bi = *(const float2*)&bias[n];
                    const float2 r2 = *(const float2*)&res[(long)m * 1024 + n];
                    float2 o; o.x = v0 + bi.x + r2.x; o.y = v1 + bi.y + r2.y;
                    *(float2*)&C[(long)m * 1024 + n] = o;
                }
            }
        }
    }
}

// ---------------- HMMA attention, 32 q-rows/block, 3-stage KV, packed P ----------------
#define AT_QH 0
#define AT_QL 4608
#define AT_KV 9216
#define AT_KVS 18432
#define AT_SS 64512
#define SSPW 1034
#define ATTN_SMEM (AT_SS + 32 * SSPW * 4)   // 196864

__global__ void __launch_bounds__(256) attn2(
    const __nv_bfloat16* __restrict__ qh, const __nv_bfloat16* __restrict__ ql,
    const __nv_bfloat16* __restrict__ kh, const __nv_bfloat16* __restrict__ kl,
    const __nv_bfloat16* __restrict__ vh, const __nv_bfloat16* __restrict__ vl,
    const unsigned char* __restrict__ mask,
    float* __restrict__ att,
    __nv_bfloat16* __restrict__ oh, __nv_bfloat16* __restrict__ ol)
{
    extern __shared__ __align__(128) char sm[];
    __shared__ int s_any;
    const uint32_t sbase = cvta_s(sm);
    const int tid = threadIdx.x;
    const int lane = tid & 31, w = tid >> 5;
    const int wm = w >> 2, wn = w & 3;
    const int qt = blockIdx.x, bh = blockIdx.y;
    const int b = bh >> 4, h = bh & 15;
    const int q0 = qt * 32;
    const long base = (long)bh * SEQ * 64;
    const float scale = 1.0f / (8.0f + 1e-6f);
    float* Ss = (float*)(sm + AT_SS);

    auto fillKV = [&](const __nv_bfloat16* phi_, const __nv_bfloat16* plo_, int buf, int kt) {
#pragma unroll
        for (int i = 0; i < 4; i++) {
            const int idx = i * 256 + tid;
            const int arr = idx >> 9;
            const int wi = idx & 511;
            const int row = wi >> 3, seg = wi & 7;
            const __nv_bfloat16* g = (arr ? plo_ : phi_) + base + (long)(kt * 64 + row) * 64 + seg * 8;
            cp16(sbase + AT_KV + buf * AT_KVS + arr * 9216 + row * 144 + seg * 16, g);
        }
        CP_COMMIT();
    };

    // Q hi/lo (joins K0's commit group)
#pragma unroll
    for (int i = 0; i < 2; i++) {
        const int idx = i * 256 + tid;
        const int arr = idx >> 8;
        const int wi = idx & 255;
        const int row = wi >> 3, seg = wi & 7;
        const __nv_bfloat16* g = (arr ? ql : qh) + base + (long)(q0 + row) * 64 + seg * 8;
        cp16(sbase + (arr ? AT_QL : AT_QH) + row * 144 + seg * 16, g);
    }
    if (tid == 0) s_any = 0;

    const int kt_max = (q0 + 31) >> 6;
    const int NC = kt_max + 1;

    fillKV(kh, kl, 0, 0);
    if (NC > 1) fillKV(kh, kl, 1, 1);

    if (tid < 32 && mask[b * SEQ + q0 + tid]) s_any = 1;

    // ---- phase 1: scores (1 barrier/chunk, fills 2 ahead) ----
    uint32_t ah[4][4], al[4][4];
    int buf = 0;
    for (int kt = 0; kt < NC; kt++) {
        if (kt < NC - 1) CP_WAIT1(); else CP_WAIT0();
        __syncthreads();
        if (kt + 2 < NC) {
            int nb = buf + 2; if (nb >= 3) nb -= 3;
            fillKV(kh, kl, nb, kt + 2);
        }
        if (kt == 0) {
#pragma unroll
            for (int s = 0; s < 4; s++) {
                const uint32_t qa = sbase + (wm * 16 + (lane & 15)) * 144 + s * 32 + (lane >> 4) * 16;
                ldsm4(ah[s], qa + AT_QH);
                ldsm4(al[s], qa + AT_QL);
            }
        }
        const uint32_t khb = sbase + AT_KV + buf * AT_KVS;
        const int le = lane & 15;
#pragma unroll
        for (int j = 0; j < 2; j++) {
            float c[4] = {0, 0, 0, 0};
#pragma unroll
            for (int s = 0; s < 4; s++) {
                uint32_t bhr[2], blr[2];
                const uint32_t ka = khb + (wn * 16 + j * 8 + (le & 7)) * 144 + s * 32 + ((le >> 3) & 1) * 16;
                ldsm2(bhr, ka);
                ldsm2(blr, ka + 9216);
                mma_bf16(c, ah[s], bhr);
                mma_bf16(c, ah[s], blr);
                mma_bf16(c, al[s], bhr);
            }
            const int r = wm * 16 + (lane >> 2);
            const int col = kt * 64 + wn * 16 + j * 8 + (lane & 3) * 2;
            float2 st0; st0.x = c[0] * scale; st0.y = c[1] * scale;
            float2 st1; st1.x = c[2] * scale; st1.y = c[3] * scale;
            *(float2*)(Ss + r * SSPW + col) = st0;
            *(float2*)(Ss + (r + 8) * SSPW + col) = st1;
        }
        if (++buf == 3) buf = 0;
    }
    __syncthreads();

    const int kt_end = s_any ? (SEQ / 64 - 1) : kt_max;
    const int AVNC = kt_end + 1;

    // prefetch V chunks 0,1 under softmax
    fillKV(vh, vl, 0, 0);
    if (AVNC > 1) fillKV(vh, vl, 1, 1);

    // ---- phase 2: softmax (8 threads/row), pack p -> (bf16 hi, bf16 lo) in place ----
    {
        const int r = tid >> 3, tc = tid & 7;
        const int qg = q0 + r;
        const int limit = qg;
        const bool rmask = mask[b * SEQ + qg] != 0;
        float* srow = Ss + r * SSPW;

        float mx = -3.4e38f;
#pragma unroll 4
        for (int j = 0; j < 128; j++) {
            const int k = tc + (j << 3);
            if (k <= limit) mx = fmaxf(mx, srow[k]);
        }
#pragma unroll
        for (int off = 4; off; off >>= 1)
            mx = fmaxf(mx, __shfl_xor_sync(0xffffffffu, mx, off, 8));

        float l = 0.0f;
#pragma unroll 4
        for (int j = 0; j < 128; j++) {
            const int k = tc + (j << 3);
            if (k <= limit) {
                const float e = fast_exp(srow[k] - mx);
                srow[k] = e;
                l += e;
            }
        }
#pragma unroll
        for (int off = 4; off; off >>= 1)
            l += __shfl_xor_sync(0xffffffffu, l, off, 8);
        const float inv = 1.0f / l;
        const float invS = 1.0f / (float)SEQ;

        float* attrow = att + ((long)bh * SEQ + qg) * SEQ;
        uint32_t* prow = (uint32_t*)srow;
#pragma unroll 4
        for (int j = 0; j < 128; j++) {
            const int k = tc + (j << 3);
            float p;
            if (rmask)           p = invS;
            else if (k <= limit) p = srow[k] * inv;
            else                 p = 0.0f;
            attrow[k] = p;
            const __nv_bfloat16 phi = __float2bfloat16(p);
            const __nv_bfloat16 plo = __float2bfloat16(p - __bfloat162float(phi));
            prow[k] = (uint32_t)__bfloat16_as_ushort(phi) |
                      ((uint32_t)__bfloat16_as_ushort(plo) << 16);
        }
    }
    __syncthreads();

    // ---- phase 3: AV (1 barrier/chunk) ----
    float oacc[2][4];
#pragma unroll
    for (int j = 0; j < 2; j++)
#pragma unroll
        for (int k = 0; k < 4; k++) oacc[j][k] = 0.0f;

    const int g = lane >> 2, t4 = lane & 3;
    buf = 0;
    for (int kt = 0; kt < AVNC; kt++) {
        if (kt < AVNC - 1) CP_WAIT1(); else CP_WAIT0();
        __syncthreads();
        if (kt + 2 < AVNC) {
            int nb = buf + 2; if (nb >= 3) nb -= 3;
            fillKV(vh, vl, nb, kt + 2);
        }
        const uint32_t vbh = sbase + AT_KV + buf * AT_KVS;
#pragma unroll
        for (int s = 0; s < 4; s++) {
            uint32_t pa[4], pb[4];
#pragma unroll
            for (int kk = 0; kk < 2; kk++) {
#pragma unroll
                for (int mi = 0; mi < 2; mi++) {
                    const int row = wm * 16 + g + mi * 8;
                    const int col = kt * 64 + s * 16 + kk * 8 + t4 * 2;
                    const uint2 ww = *(const uint2*)(Ss + row * SSPW + col);
                    const int fi = kk * 2 + mi;
                    pa[fi] = __byte_perm(ww.x, ww.y, 0x5410);
                    pb[fi] = __byte_perm(ww.x, ww.y, 0x7632);
                }
            }
#pragma unroll
            for (int j = 0; j < 2; j++) {
                uint32_t vvh[2], vvl[2];
                const uint32_t va = vbh + (s * 16 + (lane & 15)) * 144 + wn * 32 + j * 16;
                ldsm2t(vvh, va);
                ldsm2t(vvl, va + 9216);
                mma_bf16(oacc[j], pa, vvh);
                mma_bf16(oacc[j], pa, vvl);
                mma_bf16(oacc[j], pb, vvh);
            }
        }
        if (++buf == 3) buf = 0;
    }

    // epilogue: bf16 hi/lo direct to [M][1024]
#pragma unroll
    for (int j = 0; j < 2; j++) {
        const int dv = h * 64 + wn * 16 + j * 8 + t4 * 2;
        const long off0 = ((long)(b * SEQ + q0 + wm * 16 + g)) * 1024 + dv;
        const long off1 = ((long)(b * SEQ + q0 + wm * 16 + g + 8)) * 1024 + dv;
        __nv_bfloat162 h2, l2;
        split2(oacc[j][0], oacc[j][1], h2, l2);
        *(__nv_bfloat162*)(oh + off0) = h2;
        *(__nv_bfloat162*)(ol + off0) = l2;
        split2(oacc[j][2], oacc[j][3], h2, l2);
        *(__nv_bfloat162*)(oh + off1) = h2;
        *(__nv_bfloat162*)(ol + off1) = l2;
    }
}

// ---------------- layernorm ----------------
template<bool SPLIT>
__global__ void __launch_bounds__(256) ln_kernel(
    const float* __restrict__ x, const float* __restrict__ gam,
    const float* __restrict__ bet, float* __restrict__ out,
    __nv_bfloat16* __restrict__ ohi, __nv_bfloat16* __restrict__ olo)
{
    __shared__ float red[256];
    const int row = blockIdx.x, tid = threadIdx.x;
    const float4 v = ((const float4*)x)[(long)row * 256 + tid];
    red[tid] = v.x + v.y + v.z + v.w;
    __syncthreads();
#pragma unroll
    for (int off = 128; off; off >>= 1) {
        if (tid < off) red[tid] += red[tid + off];
        __syncthreads();
    }
    const float mu = red[0] * (1.0f / 1024.0f);
    __syncthreads();
    const float dx = v.x - mu, dy = v.y - mu, dz = v.z - mu, dw = v.w - mu;
    red[tid] = dx * dx + dy * dy + dz * dz + dw * dw;
    __syncthreads();
#pragma unroll
    for (int off = 128; off; off >>= 1) {
        if (tid < off) red[tid] += red[tid + off];
        __syncthreads();
    }
    const float var = red[0] * (1.0f / 1024.0f);
    const float rs = rsqrtf(var + 1e-5f);
    const float4 g4 = ((const float4*)gam)[tid];
    const float4 b4 = ((const float4*)bet)[tid];
    float4 o;
    o.x = g4.x * dx * rs + b4.x;
    o.y = g4.y * dy * rs + b4.y;
    o.z = g4.z * dz * rs + b4.z;
    o.w = g4.w * dw * rs + b4.w;
    ((float4*)out)[(long)row * 256 + tid] = o;
    if (SPLIT) {
        const long i = (long)row * 256 + tid;
        __nv_bfloat162 hA, lA, hB, lB;
        split2(o.x, o.y, hA, lA);
        split2(o.z, o.w, hB, lB);
        ((__nv_bfloat162*)ohi)[i*2]   = hA;
        ((__nv_bfloat162*)ohi)[i*2+1] = hB;
        ((__nv_bfloat162*)olo)[i*2]   = lA;
        ((__nv_bfloat162*)olo)[i*2+1] = lB;
    }
}

// ---------------- launch ----------------
extern "C" void kernel_launch(void* const* d_in, const int* in_sizes, int n_in,
                              void* d_out, int out_size) {
    const float* Qin  = (const float*)d_in[0];
    const float* Kin  = (const float*)d_in[1];
    const float* Vin  = (const float*)d_in[2];
    const unsigned char* mask = (const unsigned char*)d_in[3];
    const float* W_q  = (const float*)d_in[4];
    const float* W_k  = (const float*)d_in[5];
    const float* W_v  = (const float*)d_in[6];
    const float* W_o  = (const float*)d_in[7];
    const float* w1   = (const float*)d_in[8];
    const float* b1   = (const float*)d_in[9];
    const float* w2   = (const float*)d_in[10];
    const float* b2   = (const float*)d_in[11];
    const float* ln_g = (const float*)d_in[12];
    const float* ln_b = (const float*)d_in[13];

    float *y_, *x_, *attfb_;
    cudaGetSymbolAddress((void**)&y_, g_y);
    cudaGetSymbolAddress((void**)&x_, g_x);
    cudaGetSymbolAddress((void**)&attfb_, g_att_fb);

    __nv_bfloat16 *ahi, *alo, *qh_, *ql_, *kh_, *kl_, *vh_, *vl_;
    __nv_bfloat16 *wqh, *wql, *wkh, *wkl, *wvh, *wvl, *woh, *wol, *w1h, *w1l, *w2h, *w2l;
    cudaGetSymbolAddress((void**)&ahi, g_ahi);
    cudaGetSymbolAddress((void**)&alo, g_alo);
    cudaGetSymbolAddress((void**)&qh_, g_qh); cudaGetSymbolAddress((void**)&ql_, g_ql);
    cudaGetSymbolAddress((void**)&kh_, g_kh); cudaGetSymbolAddress((void**)&kl_, g_kl);
    cudaGetSymbolAddress((void**)&vh_, g_vh); cudaGetSymbolAddress((void**)&vl_, g_vl);
    cudaGetSymbolAddress((void**)&wqh, g_wqh); cudaGetSymbolAddress((void**)&wql, g_wql);
    cudaGetSymbolAddress((void**)&wkh, g_wkh); cudaGetSymbolAddress((void**)&wkl, g_wkl);
    cudaGetSymbolAddress((void**)&wvh, g_wvh); cudaGetSymbolAddress((void**)&wvl, g_wvl);
    cudaGetSymbolAddress((void**)&woh, g_woh); cudaGetSymbolAddress((void**)&wol, g_wol);
    cudaGetSymbolAddress((void**)&w1h, g_w1h); cudaGetSymbolAddress((void**)&w1l, g_w1l);
    cudaGetSymbolAddress((void**)&w2h, g_w2h); cudaGetSymbolAddress((void**)&w2l, g_w2l);

    __nv_bfloat16* kinh = (__nv_bfloat16*)y_;
    __nv_bfloat16* kinl = kinh + OUT_MAIN;
    __nv_bfloat16* vinh = (__nv_bfloat16*)x_;
    __nv_bfloat16* vinl = vinh + OUT_MAIN;

    float* out = (float*)d_out;
    float* att = (out_size >= (int)(OUT_MAIN + OUT_ATT)) ? (out + OUT_MAIN) : attfb_;

    cudaFuncSetAttribute(mma_gemm<0>, cudaFuncAttributeMaxDynamicSharedMemorySize, GEMM_SMEM);
    cudaFuncSetAttribute(mma_gemm<1>, cudaFuncAttributeMaxDynamicSharedMemorySize, GEMM_SMEM);
    cudaFuncSetAttribute(mma_gemm<2>, cudaFuncAttributeMaxDynamicSharedMemorySize, GEMM_SMEM);
    cudaFuncSetAttribute(mma_gemm<3>, cudaFuncAttributeMaxDynamicSharedMemorySize, GEMM_SMEM);
    cudaFuncSetAttribute(attn2, cudaFuncAttributeMaxDynamicSharedMemorySize, ATTN_SMEM);

    split_transpose4<<<dim3(32, 32, 4), dim3(32, 8)>>>(
        W_q, W_k, W_v, W_o, wqh, wql, wkh, wkl, wvh, wvl, woh, wol);
    splitmulti<<<dim3(DM * DM / 1024, 2), 256>>>(
        w1, w2, nullptr, w1h, w1l, w2h, w2l, nullptr, nullptr);
    splitmulti<<<dim3(MROWS * DM / 1024, 3), 256>>>(
        Qin, Kin, Vin, ahi, alo, kinh, kinl, vinh, vinl);

    const dim3 gG(8, 64), bG(256);
    mma_gemm<0><<<gG, bG, GEMM_SMEM>>>(ahi, alo, wqh, wql, nullptr, nullptr, nullptr, qh_, ql_);
    mma_gemm<0><<<gG, bG, GEMM_SMEM>>>(kinh, kinl, wkh, wkl, nullptr, nullptr, nullptr, kh_, kl_);
    mma_gemm<0><<<gG, bG, GEMM_SMEM>>>(vinh, vinl, wvh, wvl, nullptr, nullptr, nullptr, vh_, vl_);

    attn2<<<dim3(SEQ / 32, BB * NH), 256, ATTN_SMEM>>>(
        qh_, ql_, kh_, kl_, vh_, vl_, mask, att, ahi, alo);

    mma_gemm<1><<<gG, bG, GEMM_SMEM>>>(ahi, alo, woh, wol, y_, Qin, nullptr, nullptr, nullptr);
    ln_kernel<true><<<MROWS, 256>>>(y_, ln_g, ln_b, x_, kh_, kl_);
    mma_gemm<2><<<gG, bG, GEMM_SMEM>>>(kh_, kl_, w1h, w1l, nullptr, nullptr, b1, vh_, vl_);
    mma_gemm<3><<<gG, bG, GEMM_SMEM>>>(vh_, vl_, w2h, w2l, y_, x_, b2, nullptr, nullptr);
    ln_kernel<false><<<MROWS, 256>>>(y_, ln_g, ln_b, out, nullptr, nullptr);
}